// round 12
// baseline (speedup 1.0000x reference)
#include <cuda_runtime.h>
#include <math.h>
#include <float.h>
#include <stdint.h>

#define BB   2
#define NN   4096
#define KK   32
#define HH   64
#define WW   64
#define NOFF 127
#define NOFF2 (127*127)

#define EPS      1e-6f
#define LAMBDA0  0.001f
#define TAU2X2   4.5f
#define ETA      8.0f
#define ALPHA    10.0f
#define BETA     8.0f
#define BETAP    8.0f

#define T0   0.98f
#define CAP  512

// ---------------- static device scratch --------------------------------------
__device__ float g_ex  [NOFF*32];              // exp(-dx^2/tau) per (vx,bin)
__device__ float g_ey  [NOFF*32];              // exp(-dy^2/tau) per (vy,bin)
__device__ float g_w   [BB*NOFF2];             // per-offset value sums
__device__ float g_hbins[BB*32];
__device__ float g_Rt  [BB*NOFF2];             // R(off) per batch
__device__ float g_chiT[NOFF2];                // chi(off)
__device__ float g_vals[BB*NN*KK];
__device__ int   g_idx [BB*NN*KK];
__device__ int   g_off [BB*NN*KK];
__device__ float g_a1e [BB*NN*KK];
__device__ float g_a2e [BB*NN*KK];
__device__ float g_m   [BB*NN];
__device__ float g_q   [BB*NN];
__device__ float g_sev [BB*NN];
__device__ float g_tev [BB*NN];

__device__ __forceinline__ float warp_sum(float x){
    #pragma unroll
    for(int o=16;o;o>>=1) x += __shfl_xor_sync(0xffffffffu,x,o);
    return x;
}
__device__ __forceinline__ float warp_max(float x){
    #pragma unroll
    for(int o=16;o;o>>=1) x = fmaxf(x,__shfl_xor_sync(0xffffffffu,x,o));
    return x;
}

// ---------------- K0: separable exp tables + zero scratch ---------------------
__global__ void k_exp(const float* __restrict__ bins){
    int t = blockIdx.x*blockDim.x + threadIdx.x;
    if(t < NOFF*32){
        int v = t >> 5, o = t & 31;
        float d = (float)(v-63);
        float dx = d - bins[o*2+0];
        float dy = d - bins[o*2+1];
        g_ex[t] = __expf(-dx*dx/TAU2X2);
        g_ey[t] = __expf(-dy*dy/TAU2X2);
    }
    for(int u=t; u<BB*NOFF2; u+=gridDim.x*blockDim.x) g_w[u]=0.f;
    if(t < BB*NN) g_tev[t] = 0.f;
    if(t < BB*32) g_hbins[t] = 0.f;
}

// ---------------- K1: top-32 per row (threshold + bitonic) + w-scatter --------
__global__ void k_topk(const float* __restrict__ A0){
    __shared__ float cv[CAP];
    __shared__ int   ci[CAP];
    __shared__ int   cnt;
    __shared__ float topv[KK];
    __shared__ int   topi[KK];
    __shared__ float srow[NN];           // fallback only
    __shared__ float wvs[8];
    __shared__ int   wis[8];

    const int row = blockIdx.x;
    const int tid = threadIdx.x;
    const float4* a4 = (const float4*)(A0 + (size_t)row*NN);
    if(tid==0) cnt = 0;
    __syncthreads();

    #pragma unroll
    for(int k=0;k<4;k++){
        float4 f = __ldcs(&a4[k*256 + tid]);
        float mm = fmaxf(fmaxf(f.x,f.y), fmaxf(f.z,f.w));
        if(mm > T0){
            int jb = (k*256 + tid)*4;
            if(f.x>T0){ int p=atomicAdd(&cnt,1); if(p<CAP){cv[p]=f.x; ci[p]=jb+0;} }
            if(f.y>T0){ int p=atomicAdd(&cnt,1); if(p<CAP){cv[p]=f.y; ci[p]=jb+1;} }
            if(f.z>T0){ int p=atomicAdd(&cnt,1); if(p<CAP){cv[p]=f.z; ci[p]=jb+2;} }
            if(f.w>T0){ int p=atomicAdd(&cnt,1); if(p<CAP){cv[p]=f.w; ci[p]=jb+3;} }
        }
    }
    __syncthreads();
    const int C = cnt;

    if(C >= KK && C <= 128){
        if(tid >= C && tid < 128){ cv[tid] = -FLT_MAX; ci[tid] = 0x7fffffff; }
        __syncthreads();
        #pragma unroll
        for(int k=2;k<=128;k<<=1){
            for(int j=k>>1;j>0;j>>=1){
                int ixj = tid ^ j;
                if(ixj > tid && tid < 128){
                    bool up = ((tid & k) == 0);
                    float va=cv[tid], vb=cv[ixj];
                    int   ia=ci[tid], ib=ci[ixj];
                    bool aFirst = (va>vb) || (va==vb && ia<ib);
                    if(up ? !aFirst : aFirst){
                        cv[tid]=vb; ci[tid]=ib; cv[ixj]=va; ci[ixj]=ia;
                    }
                }
                __syncthreads();
            }
        }
        if(tid<KK){ topv[tid]=cv[tid]; topi[tid]=ci[tid]; }
    } else if(C > 128 && C <= 256){
        if(tid >= C && tid < 256){ cv[tid] = -FLT_MAX; ci[tid] = 0x7fffffff; }
        __syncthreads();
        #pragma unroll
        for(int k=2;k<=256;k<<=1){
            for(int j=k>>1;j>0;j>>=1){
                int ixj = tid ^ j;
                if(ixj > tid && tid < 256){
                    bool up = ((tid & k) == 0);
                    float va=cv[tid], vb=cv[ixj];
                    int   ia=ci[tid], ib=ci[ixj];
                    bool aFirst = (va>vb) || (va==vb && ia<ib);
                    if(up ? !aFirst : aFirst){
                        cv[tid]=vb; ci[tid]=ib; cv[ixj]=va; ci[ixj]=ia;
                    }
                }
                __syncthreads();
            }
        }
        if(tid<KK){ topv[tid]=cv[tid]; topi[tid]=ci[tid]; }
    } else if(C > 256 && C <= CAP){
        if(tid < 32){
            const int lane = tid;
            for(int it=0; it<KK; ++it){
                float bv = -FLT_MAX; int bi = 0x7fffffff;
                for(int t=lane; t<C; t+=32){
                    float v = cv[t]; int j = ci[t];
                    if(v>bv || (v==bv && j<bi)){ bv=v; bi=j; }
                }
                #pragma unroll
                for(int o=16;o;o>>=1){
                    float ov = __shfl_down_sync(0xffffffffu,bv,o);
                    int   oi = __shfl_down_sync(0xffffffffu,bi,o);
                    if(ov>bv || (ov==bv && oi<bi)){ bv=ov; bi=oi; }
                }
                bv = __shfl_sync(0xffffffffu,bv,0);
                bi = __shfl_sync(0xffffffffu,bi,0);
                if(lane==0){ topv[it]=bv; topi[it]=bi; }
                for(int t=lane; t<C; t+=32) if(ci[t]==bi) cv[t] = -FLT_MAX;
                __syncwarp();
            }
        }
    } else {
        for(int t=tid; t<NN/4; t+=256) ((float4*)srow)[t] = a4[t];
        __syncthreads();
        const int warp = tid>>5, lane = tid&31, base = warp*512;
        for(int it=0; it<KK; ++it){
            float bv=-FLT_MAX; int bi=0x7fffffff;
            #pragma unroll
            for(int t=0;t<16;t++){
                int j = base + t*32 + lane;
                float v = srow[j];
                if(v>bv || (v==bv && j<bi)){ bv=v; bi=j; }
            }
            #pragma unroll
            for(int o=16;o;o>>=1){
                float ov = __shfl_down_sync(0xffffffffu,bv,o);
                int   oi = __shfl_down_sync(0xffffffffu,bi,o);
                if(ov>bv || (ov==bv && oi<bi)){ bv=ov; bi=oi; }
            }
            if(lane==0){ wvs[warp]=bv; wis[warp]=bi; }
            __syncthreads();
            if(tid==0){
                float mv=wvs[0]; int mi=wis[0];
                #pragma unroll
                for(int w=1;w<8;w++)
                    if(wvs[w]>mv || (wvs[w]==mv && wis[w]<mi)){ mv=wvs[w]; mi=wis[w]; }
                topv[it]=mv; topi[it]=mi; srow[mi]=-FLT_MAX;
            }
            __syncthreads();
        }
    }
    __syncthreads();

    if(tid < KK){
        const size_t e = (size_t)row*KK + tid;
        float v = topv[tid];
        int   j = topi[tid];
        g_vals[e] = v;
        g_idx [e] = j;
        int i  = row & (NN-1);
        int vx = (j&63) - (i&63);
        int vy = (j>>6) - (i>>6);
        int off = (vy+63)*NOFF + (vx+63);
        g_off[e] = off;
        atomicAdd(&g_w[(row>>12)*NOFF2 + off], v);
    }
}

// ---------------- K2: Hbins via separable two-stage ---------------------------
__global__ void k_mat(){
    const int b  = blockIdx.x / NOFF;
    const int vy = blockIdx.x % NOFF;
    const int lane = threadIdx.x & 31;
    const int warp = threadIdx.x >> 5;
    const float* wrow = g_w + (size_t)b*NOFF2 + vy*NOFF;
    float acc = 0.f;
    for(int vx = warp*32; vx < min(warp*32+32, NOFF); vx++){
        acc = fmaf(wrow[vx], g_ex[vx*32+lane], acc);
    }
    __shared__ float sh[4][32];
    sh[warp][lane] = acc;
    __syncthreads();
    if(warp==0){
        float t = sh[0][lane]+sh[1][lane]+sh[2][lane]+sh[3][lane];
        t *= g_ey[vy*32+lane];
        atomicAdd(&g_hbins[b*32+lane], t);
    }
}

// ---------------- K3: per-offset R & chi tables (direct vectorized loads) -----
__global__ void k_wtab(){
    __shared__ float sw0[32], sw1[32], swm[32];
    const int tid = threadIdx.x;
    if(tid < 32){
        int lane = tid;
        float h0 = g_hbins[lane];
        float h1 = g_hbins[32+lane];
        float x0 = ETA*h0, x1 = ETA*h1;
        float e0 = __expf(x0 - warp_max(x0));
        float e1 = __expf(x1 - warp_max(x1));
        float w0 = __fdividef(e0, warp_sum(e0));
        float w1 = __fdividef(e1, warp_sum(e1));
        sw0[lane]=w0; sw1[lane]=w1; swm[lane]=0.5f*(w0+w1);
    }
    __syncthreads();
    const int off = blockIdx.x*blockDim.x + tid;
    if(off < NOFF2){
        const int vx = off % NOFF, vy = off / NOFF;
        const float4* exr = (const float4*)(g_ex + vx*32);
        const float4* eyr = (const float4*)(g_ey + vy*32);
        float r0=0.f, r1=0.f, cc=0.f;
        #pragma unroll
        for(int t=0;t<8;t++){
            float4 fx = exr[t];
            float4 fy = eyr[t];
            float k0 = fx.x*fy.x, k1 = fx.y*fy.y, k2 = fx.z*fy.z, k3 = fx.w*fy.w;
            int o = 4*t;
            r0 = fmaf(sw0[o+0],k0, fmaf(sw0[o+1],k1, fmaf(sw0[o+2],k2, fmaf(sw0[o+3],k3, r0))));
            r1 = fmaf(sw1[o+0],k0, fmaf(sw1[o+1],k1, fmaf(sw1[o+2],k2, fmaf(sw1[o+3],k3, r1))));
            cc = fmaf(swm[o+0],k0, fmaf(swm[o+1],k1, fmaf(swm[o+2],k2, fmaf(swm[o+3],k3, cc))));
        }
        g_Rt[off]       = LAMBDA0 + r0;
        g_Rt[NOFF2+off] = LAMBDA0 + r1;
        g_chiT[off]     = cc;
    }
}

// ---------------- K4: per-row warp: A1, entropy->U ----------------------------
__global__ void k_row1(float* __restrict__ outU){
    const int warp = threadIdx.x>>5, lane = threadIdx.x&31;
    const int row  = blockIdx.x*8 + warp;
    const int b    = row >> 12;
    const size_t e = (size_t)row*KK + lane;
    const int off  = g_off[e];
    const float r  = g_Rt[b*NOFF2 + off];
    const float val= g_vals[e];
    float ta = val*r;
    float S  = warp_sum(ta);
    float a1 = __fdividef(ta, S+EPS);
    g_a1e[e]=a1;
    float x  = ALPHA*a1;
    float mx = warp_max(x);
    float ex = __expf(x-mx);
    float se = warp_sum(ex);
    float p  = __fdividef(ex, se);
    float t  = p*__logf(p+EPS);
    float ent= -warp_sum(t);
    float U  = __fdividef(1.f, 1.f+__expf(ent));
    if(lane==0){ outU[row]=U; g_m[row]=1.f-U; }
}

// ---------------- K5: per-row block: A2 edges, direct dense write, q ----------
__global__ void k_row2(float* __restrict__ outA2){
    __shared__ float sfin[KK];
    __shared__ int   sidx[KK];
    const int row = blockIdx.x;
    const int b   = row >> 12;
    const int tid = threadIdx.x;
    float* orow = outA2 + (size_t)row*NN;

    if(tid<32){
        const int lane=tid;
        const size_t e = (size_t)row*KK + lane;
        int   j  = g_idx[e];
        float a1 = g_a1e[e];
        float mi = g_m[row];
        float mj = g_m[(b<<12)+j];
        float hat= mi*a1*mj;
        float hs = warp_sum(hat);
        float a2 = __fdividef(hat, hs+EPS);
        float rs = warp_sum(a2);
        float fin= __fdividef(a2, rs+EPS);
        g_a2e[e]=fin;
        sidx[lane]=j; sfin[lane]=fin;
        float x  = BETAP*a2;
        float mx = warp_max(x);
        float ex = __expf(x-mx);
        float se = warp_sum(ex);
        float wlc= __fdividef(ex, se);
        float chi= g_chiT[g_off[e]];
        float q  = warp_sum(wlc*chi);
        if(lane==0) g_q[row]=q;
    }
    // zero the dense row directly in global
    float4 z = make_float4(0.f,0.f,0.f,0.f);
    for(int t=tid; t<NN/4; t+=256) ((float4*)orow)[t]=z;
    __syncthreads();
    // overwrite the 32 edge positions
    if(tid<32) orow[sidx[tid]] = sfin[tid];
}

// ---------------- K6: directional evidence (sparse reverse lookup) ------------
__global__ void k_dir(){
    const int lane = threadIdx.x & 31;
    const int row  = blockIdx.x*8 + (threadIdx.x>>5);
    const size_t e = (size_t)row*KK + lane;
    int b = row>>12, r = row&(NN-1);
    int c = g_idx[e];
    float val = g_a2e[e];
    const size_t crow = ((size_t)(b<<12)+c)*KK;
    const int4* nb = (const int4*)(g_idx + crow);
    int slot = -1;
    #pragma unroll
    for(int t=0;t<8;t++){
        int4 v = nb[t];
        if(v.x==r) slot = 4*t+0;
        if(v.y==r) slot = 4*t+1;
        if(v.z==r) slot = 4*t+2;
        if(v.w==r) slot = 4*t+3;
    }
    float rev = (slot>=0) ? g_a2e[crow + slot] : 0.f;
    float pd = 0.f;
    if(r != c){
        float ef = __expf(BETA*val);
        float er = __expf(BETA*rev);
        pd = __fdividef(ef, ef+er+EPS);
    }
    float s = warp_sum(val*pd);
    if(lane==0) g_sev[row]=s;
    atomicAdd(&g_tev[(b<<12)+c], val*(1.f-pd));
}

// ---------------- K7: pi + conv + sigmoid (fused) -----------------------------
__global__ void k_pi_conv(const float* __restrict__ gk,
                          float* __restrict__ outS, float* __restrict__ outT,
                          float* __restrict__ outM){
    int t = blockIdx.x*blockDim.x+threadIdx.x;
    if(t >= BB*NN) return;
    float s=g_sev[t], tt=g_tev[t];
    float ps = __fdividef(s, s+tt+EPS);
    outS[t]=ps; outT[t]=1.f-ps;

    int b = t>>12; int yx = t&(NN-1);
    int y = yx>>6, x = yx&63;
    const float* q = g_q + (b<<12);
    float acc = 0.f;
    #pragma unroll
    for(int dy=0;dy<5;dy++){
        int yy=y+dy-2;
        if(yy<0||yy>=HH) continue;
        #pragma unroll
        for(int dx=0;dx<5;dx++){
            int xx=x+dx-2;
            if(xx<0||xx>=WW) continue;
            acc = fmaf(q[yy*WW+xx], gk[dy*5+dx], acc);
        }
    }
    outM[t] = __fdividef(1.f, 1.f+__expf(-acc));
}

// ---------------- launch ------------------------------------------------------
extern "C" void kernel_launch(void* const* d_in, const int* in_sizes, int n_in,
                              void* d_out, int out_size){
    // inputs: 0=E (unused), 1=A0, 2=P, 3=bins, 4=smooth_kernel
    const float* A0   = (const float*)d_in[1];
    const float* bins = (const float*)d_in[3];
    const float* sker = (const float*)d_in[4];
    float* out = (float*)d_out;

    const size_t OFF_A2  = 0;
    const size_t OFF_U   = (size_t)BB*NN*NN;
    const size_t OFF_PS  = OFF_U  + BB*NN;
    const size_t OFF_PT  = OFF_PS + BB*NN;
    const size_t OFF_MAP = OFF_PT + BB*NN;

    k_exp  <<<64, 256>>>(bins);
    k_topk <<<BB*NN, 256>>>(A0);
    k_mat  <<<BB*NOFF, 128>>>();
    k_wtab <<<(NOFF2+255)/256, 256>>>();
    k_row1 <<<BB*NN/8, 256>>>(out + OFF_U);
    k_row2 <<<BB*NN, 256>>>(out + OFF_A2);
    k_dir  <<<BB*NN/8, 256>>>();
    k_pi_conv<<<(BB*NN+255)/256, 256>>>(sker, out + OFF_PS, out + OFF_PT, out + OFF_MAP);
}

// round 13
// speedup vs baseline: 1.1240x; 1.1240x over previous
#include <cuda_runtime.h>
#include <math.h>
#include <float.h>
#include <stdint.h>

#define BB   2
#define NN   4096
#define KK   32
#define HH   64
#define WW   64
#define NOFF 127
#define NOFF2 (127*127)

#define EPS      1e-6f
#define LAMBDA0  0.001f
#define TAU2X2   4.5f
#define ETA      8.0f
#define ALPHA    10.0f
#define BETA     8.0f
#define BETAP    8.0f

#define T0   0.98f
#define CAP  512

// ---------------- static device scratch --------------------------------------
__device__ float g_ex  [NOFF*32];
__device__ float g_ey  [NOFF*32];
__device__ float g_w   [BB*NOFF2];
__device__ float g_hbins[BB*32];
__device__ float g_Rt  [BB*NOFF2];
__device__ float g_chiT[NOFF2];
__device__ float g_vals[BB*NN*KK];
__device__ int   g_idx [BB*NN*KK];
__device__ int   g_off [BB*NN*KK];
__device__ float g_a1e [BB*NN*KK];
__device__ float g_a2e [BB*NN*KK];
__device__ float g_m   [BB*NN];
__device__ float g_q   [BB*NN];
__device__ float g_sev [BB*NN];
__device__ float g_tev [BB*NN];

__device__ __forceinline__ float warp_sum(float x){
    #pragma unroll
    for(int o=16;o;o>>=1) x += __shfl_xor_sync(0xffffffffu,x,o);
    return x;
}
__device__ __forceinline__ float warp_max(float x){
    #pragma unroll
    for(int o=16;o;o>>=1) x = fmaxf(x,__shfl_xor_sync(0xffffffffu,x,o));
    return x;
}

// ---------------- K0: separable exp tables + zero scratch ---------------------
__global__ void k_exp(const float* __restrict__ bins){
    int t = blockIdx.x*blockDim.x + threadIdx.x;
    if(t < NOFF*32){
        int v = t >> 5, o = t & 31;
        float d = (float)(v-63);
        float dx = d - bins[o*2+0];
        float dy = d - bins[o*2+1];
        g_ex[t] = __expf(-dx*dx/TAU2X2);
        g_ey[t] = __expf(-dy*dy/TAU2X2);
    }
    for(int u=t; u<BB*NOFF2; u+=gridDim.x*blockDim.x) g_w[u]=0.f;
    if(t < BB*NN) g_tev[t] = 0.f;
    if(t < BB*32) g_hbins[t] = 0.f;
}

// ---------------- K1: top-32 per row + fused zero-fill of dense A2 row --------
__global__ void k_topk(const float* __restrict__ A0, float* __restrict__ outA2){
    __shared__ float cv[CAP];
    __shared__ int   ci[CAP];
    __shared__ int   cnt;
    __shared__ float topv[KK];
    __shared__ int   topi[KK];
    __shared__ float srow[NN];           // fallback only
    __shared__ float wvs[8];
    __shared__ int   wis[8];

    const int row = blockIdx.x;
    const int tid = threadIdx.x;
    const float4* a4 = (const float4*)(A0 + (size_t)row*NN);
    if(tid==0) cnt = 0;
    __syncthreads();

    #pragma unroll
    for(int k=0;k<4;k++){
        float4 f = __ldcs(&a4[k*256 + tid]);
        float mm = fmaxf(fmaxf(f.x,f.y), fmaxf(f.z,f.w));
        if(mm > T0){
            int jb = (k*256 + tid)*4;
            if(f.x>T0){ int p=atomicAdd(&cnt,1); if(p<CAP){cv[p]=f.x; ci[p]=jb+0;} }
            if(f.y>T0){ int p=atomicAdd(&cnt,1); if(p<CAP){cv[p]=f.y; ci[p]=jb+1;} }
            if(f.z>T0){ int p=atomicAdd(&cnt,1); if(p<CAP){cv[p]=f.z; ci[p]=jb+2;} }
            if(f.w>T0){ int p=atomicAdd(&cnt,1); if(p<CAP){cv[p]=f.w; ci[p]=jb+3;} }
        }
    }
    // zero the dense A2 row now (overlaps with sort below; k_row2 scatters later)
    {
        float4 z = make_float4(0.f,0.f,0.f,0.f);
        float4* o4 = (float4*)(outA2 + (size_t)row*NN);
        #pragma unroll
        for(int k=0;k<4;k++) o4[k*256+tid] = z;
    }
    __syncthreads();
    const int C = cnt;

    if(C >= KK && C <= 128){
        // register bitonic sort of 128 (desc by val, asc idx), shfl for j<32
        float v = -FLT_MAX; int ix = 0x7fffffff;
        if(tid < 128 && tid < C){ v = cv[tid]; ix = ci[tid]; }
        int kk;
        #define BSTEP_SHFL(J) \
          if(tid<128){ \
            float pv = __shfl_xor_sync(0xffffffffu, v, (J)); \
            int   pi = __shfl_xor_sync(0xffffffffu, ix, (J)); \
            bool lower = ((tid & (J))==0); \
            float av = lower? v : pv;  int ai = lower? ix : pi; \
            float bv = lower? pv : v;  int bi = lower? pi : ix; \
            bool aF = (av>bv)||(av==bv&&ai<bi); \
            bool up = ((tid & kk)==0); \
            bool takeA = up ? (lower? aF : !aF) : (lower? !aF : aF); \
            v = takeA? av : bv; ix = takeA? ai : bi; }
        #define BSTEP_SMEM(J) \
          { if(tid<128){ cv[tid]=v; ci[tid]=ix; } \
            __syncthreads(); \
            if(tid<128){ \
              float pv = cv[tid^(J)]; int pi = ci[tid^(J)]; \
              bool lower = ((tid & (J))==0); \
              float av = lower? v : pv;  int ai = lower? ix : pi; \
              float bv = lower? pv : v;  int bi = lower? pi : ix; \
              bool aF = (av>bv)||(av==bv&&ai<bi); \
              bool up = ((tid & kk)==0); \
              bool takeA = up ? (lower? aF : !aF) : (lower? !aF : aF); \
              v = takeA? av : bv; ix = takeA? ai : bi; } \
            __syncthreads(); }
        kk=2;   BSTEP_SHFL(1);
        kk=4;   BSTEP_SHFL(2);  BSTEP_SHFL(1);
        kk=8;   BSTEP_SHFL(4);  BSTEP_SHFL(2);  BSTEP_SHFL(1);
        kk=16;  BSTEP_SHFL(8);  BSTEP_SHFL(4);  BSTEP_SHFL(2); BSTEP_SHFL(1);
        kk=32;  BSTEP_SHFL(16); BSTEP_SHFL(8);  BSTEP_SHFL(4); BSTEP_SHFL(2); BSTEP_SHFL(1);
        kk=64;  BSTEP_SMEM(32); BSTEP_SHFL(16); BSTEP_SHFL(8); BSTEP_SHFL(4); BSTEP_SHFL(2); BSTEP_SHFL(1);
        kk=128; BSTEP_SMEM(64); BSTEP_SMEM(32); BSTEP_SHFL(16);BSTEP_SHFL(8); BSTEP_SHFL(4); BSTEP_SHFL(2); BSTEP_SHFL(1);
        if(tid<KK){ topv[tid]=v; topi[tid]=ix; }
    } else if(C > 128 && C <= 256){
        if(tid >= C && tid < 256){ cv[tid] = -FLT_MAX; ci[tid] = 0x7fffffff; }
        __syncthreads();
        #pragma unroll
        for(int k=2;k<=256;k<<=1){
            for(int j=k>>1;j>0;j>>=1){
                int ixj = tid ^ j;
                if(ixj > tid && tid < 256){
                    bool up = ((tid & k) == 0);
                    float va=cv[tid], vb=cv[ixj];
                    int   ia=ci[tid], ib=ci[ixj];
                    bool aFirst = (va>vb) || (va==vb && ia<ib);
                    if(up ? !aFirst : aFirst){
                        cv[tid]=vb; ci[tid]=ib; cv[ixj]=va; ci[ixj]=ia;
                    }
                }
                __syncthreads();
            }
        }
        if(tid<KK){ topv[tid]=cv[tid]; topi[tid]=ci[tid]; }
    } else if(C > 256 && C <= CAP){
        if(tid < 32){
            const int lane = tid;
            for(int it=0; it<KK; ++it){
                float bv = -FLT_MAX; int bi = 0x7fffffff;
                for(int t=lane; t<C; t+=32){
                    float vv = cv[t]; int j = ci[t];
                    if(vv>bv || (vv==bv && j<bi)){ bv=vv; bi=j; }
                }
                #pragma unroll
                for(int o=16;o;o>>=1){
                    float ov = __shfl_down_sync(0xffffffffu,bv,o);
                    int   oi = __shfl_down_sync(0xffffffffu,bi,o);
                    if(ov>bv || (ov==bv && oi<bi)){ bv=ov; bi=oi; }
                }
                bv = __shfl_sync(0xffffffffu,bv,0);
                bi = __shfl_sync(0xffffffffu,bi,0);
                if(lane==0){ topv[it]=bv; topi[it]=bi; }
                for(int t=lane; t<C; t+=32) if(ci[t]==bi) cv[t] = -FLT_MAX;
                __syncwarp();
            }
        }
    } else {
        for(int t=tid; t<NN/4; t+=256) ((float4*)srow)[t] = a4[t];
        __syncthreads();
        const int warp = tid>>5, lane = tid&31, base = warp*512;
        for(int it=0; it<KK; ++it){
            float bv=-FLT_MAX; int bi=0x7fffffff;
            #pragma unroll
            for(int t=0;t<16;t++){
                int j = base + t*32 + lane;
                float vv = srow[j];
                if(vv>bv || (vv==bv && j<bi)){ bv=vv; bi=j; }
            }
            #pragma unroll
            for(int o=16;o;o>>=1){
                float ov = __shfl_down_sync(0xffffffffu,bv,o);
                int   oi = __shfl_down_sync(0xffffffffu,bi,o);
                if(ov>bv || (ov==bv && oi<bi)){ bv=ov; bi=oi; }
            }
            if(lane==0){ wvs[warp]=bv; wis[warp]=bi; }
            __syncthreads();
            if(tid==0){
                float mv=wvs[0]; int mi=wis[0];
                #pragma unroll
                for(int w=1;w<8;w++)
                    if(wvs[w]>mv || (wvs[w]==mv && wis[w]<mi)){ mv=wvs[w]; mi=wis[w]; }
                topv[it]=mv; topi[it]=mi; srow[mi]=-FLT_MAX;
            }
            __syncthreads();
        }
    }
    __syncthreads();

    if(tid < KK){
        const size_t e = (size_t)row*KK + tid;
        float v = topv[tid];
        int   j = topi[tid];
        g_vals[e] = v;
        g_idx [e] = j;
        int i  = row & (NN-1);
        int vx = (j&63) - (i&63);
        int vy = (j>>6) - (i>>6);
        int off = (vy+63)*NOFF + (vx+63);
        g_off[e] = off;
        atomicAdd(&g_w[(row>>12)*NOFF2 + off], v);
    }
}

// ---------------- K2: Hbins via separable two-stage ---------------------------
__global__ void k_mat(){
    const int b  = blockIdx.x / NOFF;
    const int vy = blockIdx.x % NOFF;
    const int lane = threadIdx.x & 31;
    const int warp = threadIdx.x >> 5;
    const float* wrow = g_w + (size_t)b*NOFF2 + vy*NOFF;
    float acc = 0.f;
    for(int vx = warp*32; vx < min(warp*32+32, NOFF); vx++){
        acc = fmaf(wrow[vx], g_ex[vx*32+lane], acc);
    }
    __shared__ float sh[4][32];
    sh[warp][lane] = acc;
    __syncthreads();
    if(warp==0){
        float t = sh[0][lane]+sh[1][lane]+sh[2][lane]+sh[3][lane];
        t *= g_ey[vy*32+lane];
        atomicAdd(&g_hbins[b*32+lane], t);
    }
}

// ---------------- K3: per-offset R & chi tables -------------------------------
__global__ void k_wtab(){
    __shared__ float sw0[32], sw1[32], swm[32];
    const int tid = threadIdx.x;
    if(tid < 32){
        int lane = tid;
        float h0 = g_hbins[lane];
        float h1 = g_hbins[32+lane];
        float x0 = ETA*h0, x1 = ETA*h1;
        float e0 = __expf(x0 - warp_max(x0));
        float e1 = __expf(x1 - warp_max(x1));
        float w0 = __fdividef(e0, warp_sum(e0));
        float w1 = __fdividef(e1, warp_sum(e1));
        sw0[lane]=w0; sw1[lane]=w1; swm[lane]=0.5f*(w0+w1);
    }
    __syncthreads();
    const int off = blockIdx.x*blockDim.x + tid;
    if(off < NOFF2){
        const int vx = off % NOFF, vy = off / NOFF;
        const float4* exr = (const float4*)(g_ex + vx*32);
        const float4* eyr = (const float4*)(g_ey + vy*32);
        float r0=0.f, r1=0.f, cc=0.f;
        #pragma unroll
        for(int t=0;t<8;t++){
            float4 fx = exr[t];
            float4 fy = eyr[t];
            float k0 = fx.x*fy.x, k1 = fx.y*fy.y, k2 = fx.z*fy.z, k3 = fx.w*fy.w;
            int o = 4*t;
            r0 = fmaf(sw0[o+0],k0, fmaf(sw0[o+1],k1, fmaf(sw0[o+2],k2, fmaf(sw0[o+3],k3, r0))));
            r1 = fmaf(sw1[o+0],k0, fmaf(sw1[o+1],k1, fmaf(sw1[o+2],k2, fmaf(sw1[o+3],k3, r1))));
            cc = fmaf(swm[o+0],k0, fmaf(swm[o+1],k1, fmaf(swm[o+2],k2, fmaf(swm[o+3],k3, cc))));
        }
        g_Rt[off]       = LAMBDA0 + r0;
        g_Rt[NOFF2+off] = LAMBDA0 + r1;
        g_chiT[off]     = cc;
    }
}

// ---------------- K4: per-row warp: A1, entropy->U ----------------------------
__global__ void k_row1(float* __restrict__ outU){
    const int warp = threadIdx.x>>5, lane = threadIdx.x&31;
    const int row  = blockIdx.x*8 + warp;
    const int b    = row >> 12;
    const size_t e = (size_t)row*KK + lane;
    const int off  = g_off[e];
    const float r  = g_Rt[b*NOFF2 + off];
    const float val= g_vals[e];
    float ta = val*r;
    float S  = warp_sum(ta);
    float a1 = __fdividef(ta, S+EPS);
    g_a1e[e]=a1;
    float x  = ALPHA*a1;
    float mx = warp_max(x);
    float ex = __expf(x-mx);
    float se = warp_sum(ex);
    float p  = __fdividef(ex, se);
    float t  = p*__logf(p+EPS);
    float ent= -warp_sum(t);
    float U  = __fdividef(1.f, 1.f+__expf(ent));
    if(lane==0){ outU[row]=U; g_m[row]=1.f-U; }
}

// ---------------- K5: warp-per-row: A2 edges, sparse scatter, q ---------------
__global__ void k_row2(float* __restrict__ outA2){
    const int lane = threadIdx.x & 31;
    const int row  = blockIdx.x*8 + (threadIdx.x>>5);
    const int b    = row >> 12;
    const size_t e = (size_t)row*KK + lane;
    int   j  = g_idx[e];
    float a1 = g_a1e[e];
    float mi = g_m[row];
    float mj = g_m[(b<<12)+j];
    float hat= mi*a1*mj;
    float hs = warp_sum(hat);
    float a2 = __fdividef(hat, hs+EPS);
    float rs = warp_sum(a2);
    float fin= __fdividef(a2, rs+EPS);
    g_a2e[e]=fin;
    outA2[(size_t)row*NN + j] = fin;    // row pre-zeroed in k_topk
    float x  = BETAP*a2;
    float mx = warp_max(x);
    float ex = __expf(x-mx);
    float se = warp_sum(ex);
    float wlc= __fdividef(ex, se);
    float chi= g_chiT[g_off[e]];
    float q  = warp_sum(wlc*chi);
    if(lane==0) g_q[row]=q;
}

// ---------------- K6: directional evidence (sparse reverse lookup) ------------
__global__ void k_dir(){
    const int lane = threadIdx.x & 31;
    const int row  = blockIdx.x*8 + (threadIdx.x>>5);
    const size_t e = (size_t)row*KK + lane;
    int b = row>>12, r = row&(NN-1);
    int c = g_idx[e];
    float val = g_a2e[e];
    const size_t crow = ((size_t)(b<<12)+c)*KK;
    const int4* nb = (const int4*)(g_idx + crow);
    int slot = -1;
    #pragma unroll
    for(int t=0;t<8;t++){
        int4 v = nb[t];
        if(v.x==r) slot = 4*t+0;
        if(v.y==r) slot = 4*t+1;
        if(v.z==r) slot = 4*t+2;
        if(v.w==r) slot = 4*t+3;
    }
    float rev = (slot>=0) ? g_a2e[crow + slot] : 0.f;
    float pd = 0.f;
    if(r != c){
        float ef = __expf(BETA*val);
        float er = __expf(BETA*rev);
        pd = __fdividef(ef, ef+er+EPS);
    }
    float s = warp_sum(val*pd);
    if(lane==0) g_sev[row]=s;
    atomicAdd(&g_tev[(b<<12)+c], val*(1.f-pd));
}

// ---------------- K7: pi + conv + sigmoid (fused) -----------------------------
__global__ void k_pi_conv(const float* __restrict__ gk,
                          float* __restrict__ outS, float* __restrict__ outT,
                          float* __restrict__ outM){
    int t = blockIdx.x*blockDim.x+threadIdx.x;
    if(t >= BB*NN) return;
    float s=g_sev[t], tt=g_tev[t];
    float ps = __fdividef(s, s+tt+EPS);
    outS[t]=ps; outT[t]=1.f-ps;

    int b = t>>12; int yx = t&(NN-1);
    int y = yx>>6, x = yx&63;
    const float* q = g_q + (b<<12);
    float acc = 0.f;
    #pragma unroll
    for(int dy=0;dy<5;dy++){
        int yy=y+dy-2;
        if(yy<0||yy>=HH) continue;
        #pragma unroll
        for(int dx=0;dx<5;dx++){
            int xx=x+dx-2;
            if(xx<0||xx>=WW) continue;
            acc = fmaf(q[yy*WW+xx], gk[dy*5+dx], acc);
        }
    }
    outM[t] = __fdividef(1.f, 1.f+__expf(-acc));
}

// ---------------- launch ------------------------------------------------------
extern "C" void kernel_launch(void* const* d_in, const int* in_sizes, int n_in,
                              void* d_out, int out_size){
    // inputs: 0=E (unused), 1=A0, 2=P, 3=bins, 4=smooth_kernel
    const float* A0   = (const float*)d_in[1];
    const float* bins = (const float*)d_in[3];
    const float* sker = (const float*)d_in[4];
    float* out = (float*)d_out;

    const size_t OFF_A2  = 0;
    const size_t OFF_U   = (size_t)BB*NN*NN;
    const size_t OFF_PS  = OFF_U  + BB*NN;
    const size_t OFF_PT  = OFF_PS + BB*NN;
    const size_t OFF_MAP = OFF_PT + BB*NN;

    k_exp  <<<64, 256>>>(bins);
    k_topk <<<BB*NN, 256>>>(A0, out + OFF_A2);
    k_mat  <<<BB*NOFF, 128>>>();
    k_wtab <<<(NOFF2+255)/256, 256>>>();
    k_row1 <<<BB*NN/8, 256>>>(out + OFF_U);
    k_row2 <<<BB*NN/8, 256>>>(out + OFF_A2);
    k_dir  <<<BB*NN/8, 256>>>();
    k_pi_conv<<<(BB*NN+255)/256, 256>>>(sker, out + OFF_PS, out + OFF_PT, out + OFF_MAP);
}

// round 14
// speedup vs baseline: 1.1458x; 1.0193x over previous
#include <cuda_runtime.h>
#include <math.h>
#include <float.h>
#include <stdint.h>

#define BB   2
#define NN   4096
#define KK   32
#define HH   64
#define WW   64
#define NOFF 127
#define NOFF2 (127*127)

#define EPS      1e-6f
#define LAMBDA0  0.001f
#define TAU2X2   4.5f
#define ETA      8.0f
#define ALPHA    10.0f
#define BETA     8.0f
#define BETAP    8.0f

#define T0   0.98f
#define CAP  512

// ---------------- static device scratch --------------------------------------
__device__ float g_ex  [NOFF*32];
__device__ float g_ey  [NOFF*32];
__device__ float g_w   [BB*NOFF2];
__device__ float g_hbins[BB*32];
__device__ float g_Rt  [BB*NOFF2];
__device__ float g_chiT[NOFF2];
__device__ float g_vals[BB*NN*KK];
__device__ int   g_idx [BB*NN*KK];
__device__ int   g_off [BB*NN*KK];
__device__ float g_a1e [BB*NN*KK];
__device__ float g_a2e [BB*NN*KK];
__device__ float g_m   [BB*NN];
__device__ float g_q   [BB*NN];
__device__ float g_sev [BB*NN];
__device__ float g_tev [BB*NN];

__device__ __forceinline__ float warp_sum(float x){
    #pragma unroll
    for(int o=16;o;o>>=1) x += __shfl_xor_sync(0xffffffffu,x,o);
    return x;
}
__device__ __forceinline__ float warp_max(float x){
    #pragma unroll
    for(int o=16;o;o>>=1) x = fmaxf(x,__shfl_xor_sync(0xffffffffu,x,o));
    return x;
}

// ---------------- K0: separable exp tables + zero scratch ---------------------
__global__ void k_exp(const float* __restrict__ bins){
    int t = blockIdx.x*blockDim.x + threadIdx.x;
    if(t < NOFF*32){
        int v = t >> 5, o = t & 31;
        float d = (float)(v-63);
        float dx = d - bins[o*2+0];
        float dy = d - bins[o*2+1];
        g_ex[t] = __expf(-dx*dx/TAU2X2);
        g_ey[t] = __expf(-dy*dy/TAU2X2);
    }
    for(int u=t; u<BB*NOFF2; u+=gridDim.x*blockDim.x) g_w[u]=0.f;
    if(t < BB*NN) g_tev[t] = 0.f;
    if(t < BB*32) g_hbins[t] = 0.f;
}

// ---------------- K1: top-32 per row + fused zero-fill of dense A2 row --------
__global__ void k_topk(const float* __restrict__ A0, float* __restrict__ outA2){
    __shared__ float cv[CAP];
    __shared__ int   ci[CAP];
    __shared__ int   cnt;
    __shared__ float topv[KK];
    __shared__ int   topi[KK];
    __shared__ float srow[NN];           // fallback only
    __shared__ float wvs[8];
    __shared__ int   wis[8];

    const int row = blockIdx.x;
    const int tid = threadIdx.x;
    const float4* a4 = (const float4*)(A0 + (size_t)row*NN);
    if(tid==0) cnt = 0;
    __syncthreads();

    #pragma unroll
    for(int k=0;k<4;k++){
        float4 f = __ldcs(&a4[k*256 + tid]);
        float mm = fmaxf(fmaxf(f.x,f.y), fmaxf(f.z,f.w));
        if(mm > T0){
            int jb = (k*256 + tid)*4;
            if(f.x>T0){ int p=atomicAdd(&cnt,1); if(p<CAP){cv[p]=f.x; ci[p]=jb+0;} }
            if(f.y>T0){ int p=atomicAdd(&cnt,1); if(p<CAP){cv[p]=f.y; ci[p]=jb+1;} }
            if(f.z>T0){ int p=atomicAdd(&cnt,1); if(p<CAP){cv[p]=f.z; ci[p]=jb+2;} }
            if(f.w>T0){ int p=atomicAdd(&cnt,1); if(p<CAP){cv[p]=f.w; ci[p]=jb+3;} }
        }
    }
    // zero the dense A2 row with streaming stores (keep L2 for A0 reads)
    {
        float4 z = make_float4(0.f,0.f,0.f,0.f);
        float4* o4 = (float4*)(outA2 + (size_t)row*NN);
        #pragma unroll
        for(int k=0;k<4;k++) __stcs(&o4[k*256+tid], z);
    }
    __syncthreads();
    const int C = cnt;

    if(C >= KK && C <= 128){
        // register bitonic sort of 128 (desc by val, asc idx), shfl for j<32
        float v = -FLT_MAX; int ix = 0x7fffffff;
        if(tid < 128 && tid < C){ v = cv[tid]; ix = ci[tid]; }
        int kk;
        #define BSTEP_SHFL(J) \
          if(tid<128){ \
            float pv = __shfl_xor_sync(0xffffffffu, v, (J)); \
            int   pi = __shfl_xor_sync(0xffffffffu, ix, (J)); \
            bool lower = ((tid & (J))==0); \
            float av = lower? v : pv;  int ai = lower? ix : pi; \
            float bv = lower? pv : v;  int bi = lower? pi : ix; \
            bool aF = (av>bv)||(av==bv&&ai<bi); \
            bool up = ((tid & kk)==0); \
            bool takeA = up ? (lower? aF : !aF) : (lower? !aF : aF); \
            v = takeA? av : bv; ix = takeA? ai : bi; }
        #define BSTEP_SMEM(J) \
          { if(tid<128){ cv[tid]=v; ci[tid]=ix; } \
            __syncthreads(); \
            if(tid<128){ \
              float pv = cv[tid^(J)]; int pi = ci[tid^(J)]; \
              bool lower = ((tid & (J))==0); \
              float av = lower? v : pv;  int ai = lower? ix : pi; \
              float bv = lower? pv : v;  int bi = lower? pi : ix; \
              bool aF = (av>bv)||(av==bv&&ai<bi); \
              bool up = ((tid & kk)==0); \
              bool takeA = up ? (lower? aF : !aF) : (lower? !aF : aF); \
              v = takeA? av : bv; ix = takeA? ai : bi; } \
            __syncthreads(); }
        kk=2;   BSTEP_SHFL(1);
        kk=4;   BSTEP_SHFL(2);  BSTEP_SHFL(1);
        kk=8;   BSTEP_SHFL(4);  BSTEP_SHFL(2);  BSTEP_SHFL(1);
        kk=16;  BSTEP_SHFL(8);  BSTEP_SHFL(4);  BSTEP_SHFL(2); BSTEP_SHFL(1);
        kk=32;  BSTEP_SHFL(16); BSTEP_SHFL(8);  BSTEP_SHFL(4); BSTEP_SHFL(2); BSTEP_SHFL(1);
        kk=64;  BSTEP_SMEM(32); BSTEP_SHFL(16); BSTEP_SHFL(8); BSTEP_SHFL(4); BSTEP_SHFL(2); BSTEP_SHFL(1);
        kk=128; BSTEP_SMEM(64); BSTEP_SMEM(32); BSTEP_SHFL(16);BSTEP_SHFL(8); BSTEP_SHFL(4); BSTEP_SHFL(2); BSTEP_SHFL(1);
        if(tid<KK){ topv[tid]=v; topi[tid]=ix; }
    } else if(C > 128 && C <= 256){
        if(tid >= C && tid < 256){ cv[tid] = -FLT_MAX; ci[tid] = 0x7fffffff; }
        __syncthreads();
        #pragma unroll
        for(int k=2;k<=256;k<<=1){
            for(int j=k>>1;j>0;j>>=1){
                int ixj = tid ^ j;
                if(ixj > tid && tid < 256){
                    bool up = ((tid & k) == 0);
                    float va=cv[tid], vb=cv[ixj];
                    int   ia=ci[tid], ib=ci[ixj];
                    bool aFirst = (va>vb) || (va==vb && ia<ib);
                    if(up ? !aFirst : aFirst){
                        cv[tid]=vb; ci[tid]=ib; cv[ixj]=va; ci[ixj]=ia;
                    }
                }
                __syncthreads();
            }
        }
        if(tid<KK){ topv[tid]=cv[tid]; topi[tid]=ci[tid]; }
    } else if(C > 256 && C <= CAP){
        if(tid < 32){
            const int lane = tid;
            for(int it=0; it<KK; ++it){
                float bv = -FLT_MAX; int bi = 0x7fffffff;
                for(int t=lane; t<C; t+=32){
                    float vv = cv[t]; int j = ci[t];
                    if(vv>bv || (vv==bv && j<bi)){ bv=vv; bi=j; }
                }
                #pragma unroll
                for(int o=16;o;o>>=1){
                    float ov = __shfl_down_sync(0xffffffffu,bv,o);
                    int   oi = __shfl_down_sync(0xffffffffu,bi,o);
                    if(ov>bv || (ov==bv && oi<bi)){ bv=ov; bi=oi; }
                }
                bv = __shfl_sync(0xffffffffu,bv,0);
                bi = __shfl_sync(0xffffffffu,bi,0);
                if(lane==0){ topv[it]=bv; topi[it]=bi; }
                for(int t=lane; t<C; t+=32) if(ci[t]==bi) cv[t] = -FLT_MAX;
                __syncwarp();
            }
        }
    } else {
        for(int t=tid; t<NN/4; t+=256) ((float4*)srow)[t] = a4[t];
        __syncthreads();
        const int warp = tid>>5, lane = tid&31, base = warp*512;
        for(int it=0; it<KK; ++it){
            float bv=-FLT_MAX; int bi=0x7fffffff;
            #pragma unroll
            for(int t=0;t<16;t++){
                int j = base + t*32 + lane;
                float vv = srow[j];
                if(vv>bv || (vv==bv && j<bi)){ bv=vv; bi=j; }
            }
            #pragma unroll
            for(int o=16;o;o>>=1){
                float ov = __shfl_down_sync(0xffffffffu,bv,o);
                int   oi = __shfl_down_sync(0xffffffffu,bi,o);
                if(ov>bv || (ov==bv && oi<bi)){ bv=ov; bi=oi; }
            }
            if(lane==0){ wvs[warp]=bv; wis[warp]=bi; }
            __syncthreads();
            if(tid==0){
                float mv=wvs[0]; int mi=wis[0];
                #pragma unroll
                for(int w=1;w<8;w++)
                    if(wvs[w]>mv || (wvs[w]==mv && wis[w]<mi)){ mv=wvs[w]; mi=wis[w]; }
                topv[it]=mv; topi[it]=mi; srow[mi]=-FLT_MAX;
            }
            __syncthreads();
        }
    }
    __syncthreads();

    if(tid < KK){
        const size_t e = (size_t)row*KK + tid;
        float v = topv[tid];
        int   j = topi[tid];
        g_vals[e] = v;
        g_idx [e] = j;
        int i  = row & (NN-1);
        int vx = (j&63) - (i&63);
        int vy = (j>>6) - (i>>6);
        int off = (vy+63)*NOFF + (vx+63);
        g_off[e] = off;
        atomicAdd(&g_w[(row>>12)*NOFF2 + off], v);
    }
}

// ---------------- K2: Hbins via separable two-stage ---------------------------
__global__ void k_mat(){
    const int b  = blockIdx.x / NOFF;
    const int vy = blockIdx.x % NOFF;
    const int lane = threadIdx.x & 31;
    const int warp = threadIdx.x >> 5;
    const float* wrow = g_w + (size_t)b*NOFF2 + vy*NOFF;
    float acc = 0.f;
    for(int vx = warp*32; vx < min(warp*32+32, NOFF); vx++){
        acc = fmaf(wrow[vx], g_ex[vx*32+lane], acc);
    }
    __shared__ float sh[4][32];
    sh[warp][lane] = acc;
    __syncthreads();
    if(warp==0){
        float t = sh[0][lane]+sh[1][lane]+sh[2][lane]+sh[3][lane];
        t *= g_ey[vy*32+lane];
        atomicAdd(&g_hbins[b*32+lane], t);
    }
}

// ---------------- K3: per-offset R & chi tables (64-thr blocks, wide grid) ----
__global__ void k_wtab(){
    __shared__ float sw0[32], sw1[32], swm[32];
    const int tid = threadIdx.x;
    if(tid < 32){
        int lane = tid;
        float h0 = g_hbins[lane];
        float h1 = g_hbins[32+lane];
        float x0 = ETA*h0, x1 = ETA*h1;
        float e0 = __expf(x0 - warp_max(x0));
        float e1 = __expf(x1 - warp_max(x1));
        float w0 = __fdividef(e0, warp_sum(e0));
        float w1 = __fdividef(e1, warp_sum(e1));
        sw0[lane]=w0; sw1[lane]=w1; swm[lane]=0.5f*(w0+w1);
    }
    __syncthreads();
    const int off = blockIdx.x*64 + tid;
    if(off < NOFF2){
        const int vx = off % NOFF, vy = off / NOFF;
        const float4* exr = (const float4*)(g_ex + vx*32);
        const float4* eyr = (const float4*)(g_ey + vy*32);
        float r0=0.f, r1=0.f, cc=0.f;
        #pragma unroll
        for(int t=0;t<8;t++){
            float4 fx = exr[t];
            float4 fy = eyr[t];
            float k0 = fx.x*fy.x, k1 = fx.y*fy.y, k2 = fx.z*fy.z, k3 = fx.w*fy.w;
            int o = 4*t;
            r0 = fmaf(sw0[o+0],k0, fmaf(sw0[o+1],k1, fmaf(sw0[o+2],k2, fmaf(sw0[o+3],k3, r0))));
            r1 = fmaf(sw1[o+0],k0, fmaf(sw1[o+1],k1, fmaf(sw1[o+2],k2, fmaf(sw1[o+3],k3, r1))));
            cc = fmaf(swm[o+0],k0, fmaf(swm[o+1],k1, fmaf(swm[o+2],k2, fmaf(swm[o+3],k3, cc))));
        }
        g_Rt[off]       = LAMBDA0 + r0;
        g_Rt[NOFF2+off] = LAMBDA0 + r1;
        g_chiT[off]     = cc;
    }
}

// ---------------- K4: per-row warp: A1, entropy->U ----------------------------
__global__ void k_row1(float* __restrict__ outU){
    const int warp = threadIdx.x>>5, lane = threadIdx.x&31;
    const int row  = blockIdx.x*8 + warp;
    const int b    = row >> 12;
    const size_t e = (size_t)row*KK + lane;
    const int off  = g_off[e];
    const float r  = g_Rt[b*NOFF2 + off];
    const float val= g_vals[e];
    float ta = val*r;
    float S  = warp_sum(ta);
    float a1 = __fdividef(ta, S+EPS);
    g_a1e[e]=a1;
    float x  = ALPHA*a1;
    float mx = warp_max(x);
    float ex = __expf(x-mx);
    float se = warp_sum(ex);
    float p  = __fdividef(ex, se);
    float t  = p*__logf(p+EPS);
    float ent= -warp_sum(t);
    float U  = __fdividef(1.f, 1.f+__expf(ent));
    if(lane==0){ outU[row]=U; g_m[row]=1.f-U; }
}

// ---------------- K5: warp-per-row: A2 edges, sparse scatter, q ---------------
__global__ void k_row2(float* __restrict__ outA2){
    const int lane = threadIdx.x & 31;
    const int row  = blockIdx.x*8 + (threadIdx.x>>5);
    const int b    = row >> 12;
    const size_t e = (size_t)row*KK + lane;
    int   j  = g_idx[e];
    float a1 = g_a1e[e];
    float mi = g_m[row];
    float mj = g_m[(b<<12)+j];
    float hat= mi*a1*mj;
    float hs = warp_sum(hat);
    float a2 = __fdividef(hat, hs+EPS);
    float rs = warp_sum(a2);
    float fin= __fdividef(a2, rs+EPS);
    g_a2e[e]=fin;
    __stcs(&outA2[(size_t)row*NN + j], fin);    // row pre-zeroed in k_topk
    float x  = BETAP*a2;
    float mx = warp_max(x);
    float ex = __expf(x-mx);
    float se = warp_sum(ex);
    float wlc= __fdividef(ex, se);
    float chi= g_chiT[g_off[e]];
    float q  = warp_sum(wlc*chi);
    if(lane==0) g_q[row]=q;
}

// ---------------- K6: directional evidence (sparse reverse lookup) ------------
__global__ void k_dir(){
    const int lane = threadIdx.x & 31;
    const int row  = blockIdx.x*8 + (threadIdx.x>>5);
    const size_t e = (size_t)row*KK + lane;
    int b = row>>12, r = row&(NN-1);
    int c = g_idx[e];
    float val = g_a2e[e];
    const size_t crow = ((size_t)(b<<12)+c)*KK;
    const int4* nb = (const int4*)(g_idx + crow);
    int slot = -1;
    #pragma unroll
    for(int t=0;t<8;t++){
        int4 v = nb[t];
        if(v.x==r) slot = 4*t+0;
        if(v.y==r) slot = 4*t+1;
        if(v.z==r) slot = 4*t+2;
        if(v.w==r) slot = 4*t+3;
    }
    float rev = (slot>=0) ? g_a2e[crow + slot] : 0.f;
    float pd = 0.f;
    if(r != c){
        float ef = __expf(BETA*val);
        float er = __expf(BETA*rev);
        pd = __fdividef(ef, ef+er+EPS);
    }
    float s = warp_sum(val*pd);
    if(lane==0) g_sev[row]=s;
    atomicAdd(&g_tev[(b<<12)+c], val*(1.f-pd));
}

// ---------------- K7: pi + conv + sigmoid (fused) -----------------------------
__global__ void k_pi_conv(const float* __restrict__ gk,
                          float* __restrict__ outS, float* __restrict__ outT,
                          float* __restrict__ outM){
    int t = blockIdx.x*blockDim.x+threadIdx.x;
    if(t >= BB*NN) return;
    float s=g_sev[t], tt=g_tev[t];
    float ps = __fdividef(s, s+tt+EPS);
    outS[t]=ps; outT[t]=1.f-ps;

    int b = t>>12; int yx = t&(NN-1);
    int y = yx>>6, x = yx&63;
    const float* q = g_q + (b<<12);
    float acc = 0.f;
    #pragma unroll
    for(int dy=0;dy<5;dy++){
        int yy=y+dy-2;
        if(yy<0||yy>=HH) continue;
        #pragma unroll
        for(int dx=0;dx<5;dx++){
            int xx=x+dx-2;
            if(xx<0||xx>=WW) continue;
            acc = fmaf(q[yy*WW+xx], gk[dy*5+dx], acc);
        }
    }
    outM[t] = __fdividef(1.f, 1.f+__expf(-acc));
}

// ---------------- launch ------------------------------------------------------
extern "C" void kernel_launch(void* const* d_in, const int* in_sizes, int n_in,
                              void* d_out, int out_size){
    // inputs: 0=E (unused), 1=A0, 2=P, 3=bins, 4=smooth_kernel
    const float* A0   = (const float*)d_in[1];
    const float* bins = (const float*)d_in[3];
    const float* sker = (const float*)d_in[4];
    float* out = (float*)d_out;

    const size_t OFF_A2  = 0;
    const size_t OFF_U   = (size_t)BB*NN*NN;
    const size_t OFF_PS  = OFF_U  + BB*NN;
    const size_t OFF_PT  = OFF_PS + BB*NN;
    const size_t OFF_MAP = OFF_PT + BB*NN;

    k_exp  <<<64, 256>>>(bins);
    k_topk <<<BB*NN, 256>>>(A0, out + OFF_A2);
    k_mat  <<<BB*NOFF, 128>>>();
    k_wtab <<<(NOFF2+63)/64, 64>>>();
    k_row1 <<<BB*NN/8, 256>>>(out + OFF_U);
    k_row2 <<<BB*NN/8, 256>>>(out + OFF_A2);
    k_dir  <<<BB*NN/8, 256>>>();
    k_pi_conv<<<(BB*NN+255)/256, 256>>>(sker, out + OFF_PS, out + OFF_PT, out + OFF_MAP);
}